// round 6
// baseline (speedup 1.0000x reference)
#include <cuda_runtime.h>
#include <cuda_bf16.h>
#include <cstdint>

// ---------------------------------------------------------------------------
// Problem constants
// ---------------------------------------------------------------------------
#define BATCH   2
#define VVOX    100000
#define MROWS   (BATCH * VVOX)     // 200000 voxel rows
#define GX      128
#define GY      128
#define GZ      16
#define CDIM    64
#define NQ      8192               // queries per batch
#define KP      8                  // keypoints per query
#define GRIDCELLS (BATCH * GX * GY * GZ)   // 524288

#define RBLOCKS 256                // reduction partial blocks

// ---------------------------------------------------------------------------
// Device scratch (static allocation only — no cudaMalloc allowed)
// ---------------------------------------------------------------------------
__device__ int   g_grid[GRIDCELLS];                    // dense hash: cell -> voxel row, -1 empty
__device__ float g_buf0[(size_t)MROWS * CDIM];         // conv output (raw)
__device__ float g_buf1[(size_t)MROWS * CDIM];         // bn+relu output
__device__ float g_part[RBLOCKS * 2 * CDIM];           // reduction partials (sum, sumsq)
__device__ float g_scale[CDIM];                        // folded BN scale
__device__ float g_shift[CDIM];                        // folded BN shift
__device__ float g_projWT[CDIM * CDIM];                // transposed projection weight

// ---------------------------------------------------------------------------
// Grid hash build
// ---------------------------------------------------------------------------
__global__ void init_grid_kernel()
{
    int i = blockIdx.x * 256 + threadIdx.x;
    if (i < GRIDCELLS) g_grid[i] = -1;
}

__global__ void scatter_kernel(const int* __restrict__ coords)
{
    int m = blockIdx.x * 256 + threadIdx.x;
    if (m < MROWS) {
        int x = coords[3 * m + 0];
        int y = coords[3 * m + 1];
        int z = coords[3 * m + 2];
        int b = m / VVOX;
        g_grid[((b * GX + x) * GY + y) * GZ + z] = m;
    }
}

// ---------------------------------------------------------------------------
// proj_W transpose (so the fuse kernel reads coalesced rows)
// ---------------------------------------------------------------------------
__global__ void transposeW_kernel(const float* __restrict__ W)
{
    int i = blockIdx.x * 256 + threadIdx.x;   // 0..4095
    if (i < CDIM * CDIM) {
        int c = i >> 6, j = i & 63;
        g_projWT[j * CDIM + c] = W[i];        // W[c][j] -> WT[j][c]
    }
}

// ---------------------------------------------------------------------------
// Submanifold 3x3x3 conv: out[m] = sum_k feats[nbr(m,k)] @ W[k]
// Block: 128 voxel rows x 64 output channels. 256 threads.
// Thread (tm = tid&31, tn = tid>>5) owns rows tm*4..tm*4+3, cols tn*8..tn*8+7.
// Dynamic smem: sW[64][64] (16KB) | sFT[64][128] transposed feats (32KB)
//               | sN[128] neighbor rows | sP[128] packed coords.
// ---------------------------------------------------------------------------
#define CONV_SMEM (16384 + 32768 + 512 + 512)

__global__ void __launch_bounds__(256)
conv_kernel(const float* __restrict__ fin,
            const float* __restrict__ Wall,
            const int*   __restrict__ coords,
            float*       __restrict__ fout)
{
    extern __shared__ __align__(16) char smem[];
    float* sW  = (float*)(smem);                       // 4096 floats
    float* sFT = (float*)(smem + 16384);               // 8192 floats [cin][row]
    int*   sN  = (int*)  (smem + 16384 + 32768);       // 128 ints
    int*   sP  = (int*)  (smem + 16384 + 32768 + 512); // 128 ints

    const int tid = threadIdx.x;
    const int m0  = blockIdx.x * 128;
    const int tm  = tid & 31;
    const int tn  = tid >> 5;

    if (tid < 128) {
        int r = m0 + tid;
        if (r < MROWS) {
            int x = coords[3 * r + 0];
            int y = coords[3 * r + 1];
            int z = coords[3 * r + 2];
            sP[tid] = (x << 11) | (y << 4) | z;
        } else {
            sP[tid] = -1;
        }
    }

    float acc[4][8];
#pragma unroll
    for (int i = 0; i < 4; i++)
#pragma unroll
        for (int j = 0; j < 8; j++) acc[i][j] = 0.0f;

    for (int k = 0; k < 27; ++k) {
        __syncthreads();   // previous GEMM done; also covers sP init on k==0

        // neighbor row lookup for each of the 128 voxels
        if (tid < 128) {
            int nidx = -1;
            int p = sP[tid];
            if (p >= 0) {
                int x = (p >> 11)        + (k / 9)       - 1;
                int y = ((p >> 4) & 127) + ((k / 3) % 3) - 1;
                int z = (p & 15)         + (k % 3)       - 1;
                if (((unsigned)x < (unsigned)GX) &
                    ((unsigned)y < (unsigned)GY) &
                    ((unsigned)z < (unsigned)GZ)) {
                    int b = (m0 + tid) / VVOX;
                    nidx = g_grid[((b * GX + x) * GY + y) * GZ + z];
                }
            }
            sN[tid] = nidx;
        }

        // stage W[k] (64x64) into shared
        {
            const float4* Wk  = (const float4*)(Wall + (size_t)k * 4096);
            float4*       sW4 = (float4*)sW;
#pragma unroll
            for (int i = 0; i < 4; i++)
                sW4[tid + i * 256] = Wk[tid + i * 256];
        }
        __syncthreads();

        // gather neighbor feature rows, store TRANSPOSED: sFT[cin][row]
        {
            int row  = tid & 127;
            int ch0  = (tid >> 7) << 5;   // 0 or 32
            int nidx = sN[row];
            if (nidx >= 0) {
                const float4* src = (const float4*)(fin + (size_t)nidx * CDIM + ch0);
#pragma unroll
                for (int j = 0; j < 8; j++) {
                    float4 v = src[j];
                    int c = ch0 + j * 4;
                    sFT[(c + 0) * 128 + row] = v.x;
                    sFT[(c + 1) * 128 + row] = v.y;
                    sFT[(c + 2) * 128 + row] = v.z;
                    sFT[(c + 3) * 128 + row] = v.w;
                }
            } else {
#pragma unroll
                for (int j = 0; j < 8; j++) {
                    int c = ch0 + j * 4;
                    sFT[(c + 0) * 128 + row] = 0.0f;
                    sFT[(c + 1) * 128 + row] = 0.0f;
                    sFT[(c + 2) * 128 + row] = 0.0f;
                    sFT[(c + 3) * 128 + row] = 0.0f;
                }
            }
        }
        __syncthreads();

        // 128x64x64 register-blocked FMA tile
#pragma unroll 4
        for (int ci = 0; ci < 64; ++ci) {
            float4 a  = *(const float4*)(sFT + ci * 128 + (tm << 2));  // conflict-free
            float4 bA = *(const float4*)(sW  + ci * 64  + (tn << 3));  // warp broadcast
            float4 bB = *(const float4*)(sW  + ci * 64  + (tn << 3) + 4);
            float av[4] = {a.x, a.y, a.z, a.w};
            float bv[8] = {bA.x, bA.y, bA.z, bA.w, bB.x, bB.y, bB.z, bB.w};
#pragma unroll
            for (int i = 0; i < 4; i++)
#pragma unroll
                for (int j = 0; j < 8; j++)
                    acc[i][j] = fmaf(av[i], bv[j], acc[i][j]);
        }
    }

    // write out
#pragma unroll
    for (int i = 0; i < 4; i++) {
        int r = m0 + (tm << 2) + i;
        if (r < MROWS) {
            float4 o0 = make_float4(acc[i][0], acc[i][1], acc[i][2], acc[i][3]);
            float4 o1 = make_float4(acc[i][4], acc[i][5], acc[i][6], acc[i][7]);
            float* dst = fout + (size_t)r * CDIM + (tn << 3);
            *(float4*)(dst)     = o0;
            *(float4*)(dst + 4) = o1;
        }
    }
}

// ---------------------------------------------------------------------------
// BatchNorm (training-mode batch stats) — deterministic two-stage reduction
// ---------------------------------------------------------------------------
__global__ void reduce_partial_kernel(const float* __restrict__ x)
{
    __shared__ float sh[8][CDIM];
    int tid = threadIdx.x;              // 256
    int c = tid & 63, g = tid >> 6;     // 4 row-groups
    float s = 0.0f, s2 = 0.0f;
    for (int r = blockIdx.x * 4 + g; r < MROWS; r += RBLOCKS * 4) {
        float v = x[(size_t)r * CDIM + c];
        s  += v;
        s2 += v * v;
    }
    sh[g][c]     = s;
    sh[4 + g][c] = s2;
    __syncthreads();
    if (tid < 64) {
        float a = sh[0][tid] + sh[1][tid] + sh[2][tid] + sh[3][tid];
        float b = sh[4][tid] + sh[5][tid] + sh[6][tid] + sh[7][tid];
        g_part[blockIdx.x * 128 + tid]      = a;
        g_part[blockIdx.x * 128 + 64 + tid] = b;
    }
}

__global__ void reduce_final_kernel(const float* __restrict__ gamma,
                                    const float* __restrict__ beta)
{
    int c = threadIdx.x;                // 64
    float s = 0.0f, s2 = 0.0f;
    for (int bb = 0; bb < RBLOCKS; ++bb) {
        s  += g_part[bb * 128 + c];
        s2 += g_part[bb * 128 + 64 + c];
    }
    const float invM = 1.0f / (float)MROWS;
    float mu  = s * invM;
    float var = s2 * invM - mu * mu;    // biased variance (jnp.var default)
    float r   = rsqrtf(var + 1e-5f);
    float a   = r * gamma[c];
    g_scale[c] = a;
    g_shift[c] = beta[c] - mu * a;
}

__global__ void bn_apply_kernel(const float* __restrict__ x, float* __restrict__ y, int n4)
{
    int i = blockIdx.x * blockDim.x + threadIdx.x;
    if (i >= n4) return;
    int c4 = i & 15;                    // (4 floats) position within 64-ch row
    float4 v = ((const float4*)x)[i];
    float4 a = ((const float4*)g_scale)[c4];
    float4 b = ((const float4*)g_shift)[c4];
    v.x = fmaxf(fmaf(v.x, a.x, b.x), 0.0f);
    v.y = fmaxf(fmaf(v.y, a.y, b.y), 0.0f);
    v.z = fmaxf(fmaf(v.z, a.z, b.z), 0.0f);
    v.w = fmaxf(fmaf(v.w, a.w, b.w), 0.0f);
    ((float4*)y)[i] = v;
}

// ---------------------------------------------------------------------------
// Keypoint gather + mean + residual + projection; voxel_indices emission
// One 64-thread block per query (b,n).
// ---------------------------------------------------------------------------
__global__ void fuse_kernel(const float* __restrict__ kp,
                            const float* __restrict__ qf,
                            const float* __restrict__ feats,
                            const float* __restrict__ pb,
                            float* __restrict__ outF,
                            float* __restrict__ outI,
                            int writeIdx)
{
    __shared__ float sAvg[CDIM];
    __shared__ int   sIdx[KP];
    int q   = blockIdx.x;        // 0 .. B*NQ-1
    int tid = threadIdx.x;       // 64
    int b   = q >> 13;           // NQ = 8192

    if (tid < KP) {
        const float* kpp = kp + ((size_t)q * KP + tid) * 3;
        int qx = (int)(kpp[0] * 2.0f); qx = min(max(qx, 0), GX - 1);
        int qy = (int)(kpp[1] * 2.0f); qy = min(max(qy, 0), GY - 1);
        int qz = (int)(kpp[2] * 2.0f); qz = min(max(qz, 0), GZ - 1);
        int idx = g_grid[((b * GX + qx) * GY + qy) * GZ + qz];
        sIdx[tid] = (idx < 0) ? 0 : idx;    // jnp.maximum(idx, 0) fallback row 0
        if (writeIdx) {
            float* o = outI + ((size_t)q * KP + tid) * 4;
            o[0] = (float)b;
            o[1] = (float)qx;
            o[2] = (float)qy;
            o[3] = (float)qz;
        }
    }
    __syncthreads();

    float s = 0.0f;
#pragma unroll
    for (int kk = 0; kk < KP; kk++)
        s += feats[(size_t)sIdx[kk] * CDIM + tid];
    s = s * 0.125f + qf[(size_t)q * CDIM + tid];
    sAvg[tid] = s;
    __syncthreads();

    float o = pb[tid];
#pragma unroll 8
    for (int j = 0; j < CDIM; j++)
        o = fmaf(sAvg[j], g_projWT[j * CDIM + tid], o);
    outF[(size_t)q * CDIM + tid] = o;
}

// ---------------------------------------------------------------------------
// Host launcher
// ---------------------------------------------------------------------------
extern "C" void kernel_launch(void* const* d_in, const int* in_sizes, int n_in,
                              void* d_out, int out_size)
{
    const float* keypoints = (const float*)d_in[0];
    const float* query     = (const float*)d_in[1];
    const float* vfeat     = (const float*)d_in[2];
    const int*   vcoords   = (const int*)  d_in[3];
    const float* W1        = (const float*)d_in[4];
    const float* g1        = (const float*)d_in[5];
    const float* b1        = (const float*)d_in[6];
    const float* W2        = (const float*)d_in[7];
    const float* g2        = (const float*)d_in[8];
    const float* b2        = (const float*)d_in[9];
    const float* projW     = (const float*)d_in[10];
    const float* projb     = (const float*)d_in[11];
    float* out = (float*)d_out;

    (void)in_sizes; (void)n_in;

    cudaFuncSetAttribute(conv_kernel, cudaFuncAttributeMaxDynamicSharedMemorySize, CONV_SMEM);

    float *buf0, *buf1;
    cudaGetSymbolAddress((void**)&buf0, g_buf0);
    cudaGetSymbolAddress((void**)&buf1, g_buf1);

    const int fusedElems = BATCH * NQ * CDIM;                 // 1,048,576
    const int idxElems   = BATCH * NQ * KP * 4;               // 524,288
    int writeIdx = (out_size >= fusedElems + idxElems) ? 1 : 0;

    // 1) grid hash
    init_grid_kernel<<<GRIDCELLS / 256, 256>>>();
    scatter_kernel<<<(MROWS + 255) / 256, 256>>>(vcoords);
    transposeW_kernel<<<16, 256>>>(projW);

    const int convBlocks = (MROWS + 127) / 128;               // 1563
    const int n4         = MROWS * CDIM / 4;                  // 3,200,000
    const int bnBlocks   = (n4 + 255) / 256;

    // 2) layer 1: conv -> BN(batch stats) + ReLU
    conv_kernel<<<convBlocks, 256, CONV_SMEM>>>(vfeat, W1, vcoords, buf0);
    reduce_partial_kernel<<<RBLOCKS, 256>>>(buf0);
    reduce_final_kernel<<<1, 64>>>(g1, b1);
    bn_apply_kernel<<<bnBlocks, 256>>>(buf0, buf1, n4);

    // 3) layer 2
    conv_kernel<<<convBlocks, 256, CONV_SMEM>>>(buf1, W2, vcoords, buf0);
    reduce_partial_kernel<<<RBLOCKS, 256>>>(buf0);
    reduce_final_kernel<<<1, 64>>>(g2, b2);
    bn_apply_kernel<<<bnBlocks, 256>>>(buf0, buf1, n4);

    // 4) gather + fuse + project (+ voxel_indices)
    fuse_kernel<<<BATCH * NQ, 64>>>(keypoints, query, buf1, projb,
                                    out, out + fusedElems, writeIdx);
}

// round 10
// speedup vs baseline: 1.9889x; 1.9889x over previous
#include <cuda_runtime.h>
#include <cuda_bf16.h>
#include <cstdint>

// ---------------------------------------------------------------------------
// Problem constants
// ---------------------------------------------------------------------------
#define BATCH   2
#define VVOX    100000
#define MROWS   (BATCH * VVOX)     // 200000 voxel rows
#define GX      128
#define GY      128
#define GZ      16
#define CDIM    64
#define NQ      8192
#define KP      8
#define GRIDCELLS (BATCH * GX * GY * GZ)   // 524288
#define RBLOCKS 256

// ---------------------------------------------------------------------------
// Device scratch (static allocation only)
// ---------------------------------------------------------------------------
__device__ int   g_grid[GRIDCELLS];
__device__ float g_buf0[(size_t)MROWS * CDIM];        // conv output (raw fp32)
__device__ float g_buf1[(size_t)MROWS * CDIM];        // bn+relu output / rounded input
__device__ float g_part[RBLOCKS * 2 * CDIM];
__device__ float g_scale[CDIM];
__device__ float g_shift[CDIM];
__device__ float g_projWT[CDIM * CDIM];
__device__ float g_Wst[2 * 27 * 4096];                // W as [k][cout][cin], tf32-rounded

// ---------------------------------------------------------------------------
// Helpers
// ---------------------------------------------------------------------------
__device__ __forceinline__ uint32_t smem_to_u32(const void* p) {
    uint32_t a;
    asm("{ .reg .u64 t; cvta.to.shared.u64 t, %1; cvt.u32.u64 %0, t; }" : "=r"(a) : "l"(p));
    return a;
}
__device__ __forceinline__ float tf32_round(float x) {
    uint32_t u;
    asm("cvt.rna.tf32.f32 %0, %1;" : "=r"(u) : "f"(x));
    return __uint_as_float(u);
}

#define CP_ASYNC16(dst, src) \
    asm volatile("cp.async.cg.shared.global [%0], [%1], 16;" :: "r"(dst), "l"(src) : "memory")
#define CP_COMMIT() asm volatile("cp.async.commit_group;" ::: "memory")
#define CP_WAIT0()  asm volatile("cp.async.wait_group 0;" ::: "memory")
#define STS16_ZERO(dst) \
    asm volatile("st.shared.v4.b32 [%0], {%1, %1, %1, %1};" :: "r"(dst), "r"(0u) : "memory")

// m16n8k8 tf32 MMA, fp32 accumulate, C==D in registers
__device__ __forceinline__ void mma_tf32(float* c,
                                         uint32_t a0, uint32_t a1, uint32_t a2, uint32_t a3,
                                         uint32_t b0, uint32_t b1)
{
    asm volatile("mma.sync.aligned.m16n8k8.row.col.f32.tf32.tf32.f32 "
                 "{%0,%1,%2,%3}, {%4,%5,%6,%7}, {%8,%9}, {%0,%1,%2,%3};"
                 : "+f"(c[0]), "+f"(c[1]), "+f"(c[2]), "+f"(c[3])
                 : "r"(a0), "r"(a1), "r"(a2), "r"(a3), "r"(b0), "r"(b1));
}

// ---------------------------------------------------------------------------
// Grid hash build
// ---------------------------------------------------------------------------
__global__ void init_grid_kernel()
{
    int i = blockIdx.x * 256 + threadIdx.x;
    if (i < GRIDCELLS) g_grid[i] = -1;
}

__global__ void scatter_kernel(const int* __restrict__ coords)
{
    int m = blockIdx.x * 256 + threadIdx.x;
    if (m < MROWS) {
        int x = coords[3 * m + 0];
        int y = coords[3 * m + 1];
        int z = coords[3 * m + 2];
        int b = m / VVOX;
        g_grid[((b * GX + x) * GY + y) * GZ + z] = m;
    }
}

__global__ void transposeW_kernel(const float* __restrict__ W)
{
    int i = blockIdx.x * 256 + threadIdx.x;
    if (i < CDIM * CDIM) {
        int c = i >> 6, j = i & 63;
        g_projWT[j * CDIM + c] = W[i];
    }
}

// W prep: (27, Cin, Cout) -> [k][cout][cin], tf32-rounded (B operand, col-major)
__global__ void prepW_kernel(const float* __restrict__ W, float* __restrict__ dst)
{
    int i = blockIdx.x * 256 + threadIdx.x;       // 27 * 4096
    if (i < 27 * 4096) {
        int k = i >> 12;
        int r = i & 4095;
        int cin = r >> 6, cout = r & 63;          // W[k][cin][cout]
        dst[k * 4096 + cout * 64 + cin] = tf32_round(W[i]);
    }
}

// Round fp32 -> tf32 (rna): pre-round so HW mantissa truncation is exact
__global__ void round_kernel(const float* __restrict__ x, float* __restrict__ y, int n4)
{
    int i = blockIdx.x * 256 + threadIdx.x;
    if (i >= n4) return;
    float4 v = ((const float4*)x)[i];
    v.x = tf32_round(v.x); v.y = tf32_round(v.y);
    v.z = tf32_round(v.z); v.w = tf32_round(v.w);
    ((float4*)y)[i] = v;
}

// ---------------------------------------------------------------------------
// Tensor-core submanifold conv via mma.sync tf32.
// CTA = 128 voxel rows x 64 output channels, 8 warps.
// Warp w: m-block (w&3)*32, n-block (w>>2)*32; 2x4 mma tiles x 8 k-steps.
// Accumulators live in registers across all 27 offsets.
// SMEM (floats, stride 68 rows for conflict-free fragment loads):
//   sA[128][68] | sB[64][68] | sN[128] | sP[128]
// ---------------------------------------------------------------------------
#define ASTRIDE 68
#define SA_F    0
#define SB_F    (128 * ASTRIDE)                   // 8704
#define SMEM_F  (SB_F + 64 * ASTRIDE)             // 13056 floats
#define OFF_SN  (SMEM_F * 4)                      // bytes
#define OFF_SP  (OFF_SN + 512)
#define CONV_SMEM (OFF_SP + 512)                  // 53248 B

__global__ void __launch_bounds__(256, 2)
conv_mma_kernel(const float* __restrict__ fin,
                const int*   __restrict__ coords,
                const float* __restrict__ Wst,
                float*       __restrict__ fout)
{
    extern __shared__ __align__(16) float smem[];
    const uint32_t sb = smem_to_u32(smem);

    float* sA = smem + SA_F;
    float* sB = smem + SB_F;
    int*   sN = (int*)((char*)smem + OFF_SN);
    int*   sP = (int*)((char*)smem + OFF_SP);

    const int tid = threadIdx.x;
    const int wid = tid >> 5;
    const int lid = tid & 31;
    const int m0  = blockIdx.x * 128;

    const int g = lid >> 2;          // group id 0..7
    const int t = lid & 3;           // thread-in-group
    const int mb = (wid & 3) * 32;   // warp m block
    const int nb = (wid >> 2) * 32;  // warp n block

    if (tid < 128) {
        int r = m0 + tid;
        sP[tid] = (r < MROWS)
                ? ((coords[3 * r] << 11) | (coords[3 * r + 1] << 4) | coords[3 * r + 2])
                : -1;
    }

    float acc[2][4][4];
#pragma unroll
    for (int mt = 0; mt < 2; mt++)
#pragma unroll
        for (int nt = 0; nt < 4; nt++)
#pragma unroll
            for (int i = 0; i < 4; i++) acc[mt][nt][i] = 0.0f;

    // A gather mapping: thread pair per row
    const int arow = tid >> 1;
    const int ahalf = tid & 1;       // cols 32*ahalf .. +31
    const uint32_t adst0 = sb + (uint32_t)(arow * ASTRIDE + ahalf * 32) * 4u;

    // B copy mapping: quarter-row per thread
    const int brow = tid >> 2;
    const int bpart = tid & 3;       // 16 floats
    const uint32_t bdst0 = sb + (uint32_t)(SB_F + brow * ASTRIDE + bpart * 16) * 4u;

    for (int k = 0; k < 27; ++k) {
        __syncthreads();   // prior compute done reading smem; sP ready (k==0)

        // neighbor lookup
        if (tid < 128) {
            int nidx = -1;
            int p = sP[tid];
            if (p >= 0) {
                int x = (p >> 11)        + (k / 9)       - 1;
                int y = ((p >> 4) & 127) + ((k / 3) % 3) - 1;
                int z = (p & 15)         + (k % 3)       - 1;
                if (((unsigned)x < (unsigned)GX) &
                    ((unsigned)y < (unsigned)GY) &
                    ((unsigned)z < (unsigned)GZ)) {
                    int b = (m0 + tid) / VVOX;
                    nidx = g_grid[((b * GX + x) * GY + y) * GZ + z];
                }
            }
            sN[tid] = nidx;
        }
        __syncthreads();

        // A gather: 8 x 16B per thread (half a 256B feature row)
        {
            int nidx = sN[arow];
            if (nidx >= 0) {
                const float* src = fin + (size_t)nidx * CDIM + ahalf * 32;
#pragma unroll
                for (int i = 0; i < 8; i++)
                    CP_ASYNC16(adst0 + i * 16, src + i * 4);
            } else {
#pragma unroll
                for (int i = 0; i < 8; i++)
                    STS16_ZERO(adst0 + i * 16);
            }
        }
        // B copy: W_k [64][64] -> sB stride 68
        {
            const float* srcb = Wst + k * 4096 + brow * 64 + bpart * 16;
#pragma unroll
            for (int i = 0; i < 4; i++)
                CP_ASYNC16(bdst0 + i * 16, srcb + i * 4);
        }
        CP_COMMIT();
        CP_WAIT0();
        __syncthreads();

        // compute: 8 k-steps x (2 m-tiles x 4 n-tiles) mma
#pragma unroll
        for (int s = 0; s < 8; s++) {
            const int kk = 8 * s + t;
            uint32_t b0[4], b1[4];
#pragma unroll
            for (int nt = 0; nt < 4; nt++) {
                const float* bp = sB + (nb + nt * 8 + g) * ASTRIDE;
                b0[nt] = __float_as_uint(bp[kk]);
                b1[nt] = __float_as_uint(bp[kk + 4]);
            }
#pragma unroll
            for (int mt = 0; mt < 2; mt++) {
                const float* ap = sA + (mb + mt * 16 + g) * ASTRIDE;
                uint32_t a0 = __float_as_uint(ap[kk]);
                uint32_t a1 = __float_as_uint(ap[8 * ASTRIDE + kk]);
                uint32_t a2 = __float_as_uint(ap[kk + 4]);
                uint32_t a3 = __float_as_uint(ap[8 * ASTRIDE + kk + 4]);
#pragma unroll
                for (int nt = 0; nt < 4; nt++)
                    mma_tf32(acc[mt][nt], a0, a1, a2, a3, b0[nt], b1[nt]);
            }
        }
    }

    // epilogue: c0,c1 -> (row g, cols 2t,2t+1); c2,c3 -> row g+8
#pragma unroll
    for (int mt = 0; mt < 2; mt++) {
        int r0 = m0 + mb + mt * 16 + g;
        int r1 = r0 + 8;
#pragma unroll
        for (int nt = 0; nt < 4; nt++) {
            int col = nb + nt * 8 + 2 * t;
            if (r0 < MROWS)
                *(float2*)(fout + (size_t)r0 * CDIM + col) =
                    make_float2(acc[mt][nt][0], acc[mt][nt][1]);
            if (r1 < MROWS)
                *(float2*)(fout + (size_t)r1 * CDIM + col) =
                    make_float2(acc[mt][nt][2], acc[mt][nt][3]);
        }
    }
}

// ---------------------------------------------------------------------------
// BatchNorm (training-mode batch stats) — deterministic two-stage reduction
// ---------------------------------------------------------------------------
__global__ void reduce_partial_kernel(const float* __restrict__ x)
{
    __shared__ float sh[8][CDIM];
    int tid = threadIdx.x;
    int c = tid & 63, g = tid >> 6;
    float s = 0.0f, s2 = 0.0f;
    for (int r = blockIdx.x * 4 + g; r < MROWS; r += RBLOCKS * 4) {
        float v = x[(size_t)r * CDIM + c];
        s  += v;
        s2 += v * v;
    }
    sh[g][c]     = s;
    sh[4 + g][c] = s2;
    __syncthreads();
    if (tid < 64) {
        float a = sh[0][tid] + sh[1][tid] + sh[2][tid] + sh[3][tid];
        float b = sh[4][tid] + sh[5][tid] + sh[6][tid] + sh[7][tid];
        g_part[blockIdx.x * 128 + tid]      = a;
        g_part[blockIdx.x * 128 + 64 + tid] = b;
    }
}

__global__ void reduce_final_kernel(const float* __restrict__ gamma,
                                    const float* __restrict__ beta)
{
    int c = threadIdx.x;
    float s = 0.0f, s2 = 0.0f;
    for (int bb = 0; bb < RBLOCKS; ++bb) {
        s  += g_part[bb * 128 + c];
        s2 += g_part[bb * 128 + 64 + c];
    }
    const float invM = 1.0f / (float)MROWS;
    float mu  = s * invM;
    float var = s2 * invM - mu * mu;
    float r   = rsqrtf(var + 1e-5f);
    float a   = r * gamma[c];
    g_scale[c] = a;
    g_shift[c] = beta[c] - mu * a;
}

__global__ void bn_apply_kernel(const float* __restrict__ x, float* __restrict__ y,
                                int n4, int doRound)
{
    int i = blockIdx.x * blockDim.x + threadIdx.x;
    if (i >= n4) return;
    int c4 = i & 15;
    float4 v = ((const float4*)x)[i];
    float4 a = ((const float4*)g_scale)[c4];
    float4 b = ((const float4*)g_shift)[c4];
    v.x = fmaxf(fmaf(v.x, a.x, b.x), 0.0f);
    v.y = fmaxf(fmaf(v.y, a.y, b.y), 0.0f);
    v.z = fmaxf(fmaf(v.z, a.z, b.z), 0.0f);
    v.w = fmaxf(fmaf(v.w, a.w, b.w), 0.0f);
    if (doRound) {
        v.x = tf32_round(v.x); v.y = tf32_round(v.y);
        v.z = tf32_round(v.z); v.w = tf32_round(v.w);
    }
    ((float4*)y)[i] = v;
}

// ---------------------------------------------------------------------------
// Keypoint gather + mean + residual + projection; voxel_indices emission
// ---------------------------------------------------------------------------
__global__ void fuse_kernel(const float* __restrict__ kp,
                            const float* __restrict__ qf,
                            const float* __restrict__ feats,
                            const float* __restrict__ pb,
                            float* __restrict__ outF,
                            float* __restrict__ outI,
                            int writeIdx)
{
    __shared__ float sAvg[CDIM];
    __shared__ int   sIdx[KP];
    int q   = blockIdx.x;
    int tid = threadIdx.x;
    int b   = q >> 13;

    if (tid < KP) {
        const float* kpp = kp + ((size_t)q * KP + tid) * 3;
        int qx = (int)(kpp[0] * 2.0f); qx = min(max(qx, 0), GX - 1);
        int qy = (int)(kpp[1] * 2.0f); qy = min(max(qy, 0), GY - 1);
        int qz = (int)(kpp[2] * 2.0f); qz = min(max(qz, 0), GZ - 1);
        int idx = g_grid[((b * GX + qx) * GY + qy) * GZ + qz];
        sIdx[tid] = (idx < 0) ? 0 : idx;
        if (writeIdx) {
            float* o = outI + ((size_t)q * KP + tid) * 4;
            o[0] = (float)b;
            o[1] = (float)qx;
            o[2] = (float)qy;
            o[3] = (float)qz;
        }
    }
    __syncthreads();

    float s = 0.0f;
#pragma unroll
    for (int kk = 0; kk < KP; kk++)
        s += feats[(size_t)sIdx[kk] * CDIM + tid];
    s = s * 0.125f + qf[(size_t)q * CDIM + tid];
    sAvg[tid] = s;
    __syncthreads();

    float o = pb[tid];
#pragma unroll 8
    for (int j = 0; j < CDIM; j++)
        o = fmaf(sAvg[j], g_projWT[j * CDIM + tid], o);
    outF[(size_t)q * CDIM + tid] = o;
}

// ---------------------------------------------------------------------------
// Host launcher
// ---------------------------------------------------------------------------
extern "C" void kernel_launch(void* const* d_in, const int* in_sizes, int n_in,
                              void* d_out, int out_size)
{
    const float* keypoints = (const float*)d_in[0];
    const float* query     = (const float*)d_in[1];
    const float* vfeat     = (const float*)d_in[2];
    const int*   vcoords   = (const int*)  d_in[3];
    const float* W1        = (const float*)d_in[4];
    const float* g1        = (const float*)d_in[5];
    const float* b1        = (const float*)d_in[6];
    const float* W2        = (const float*)d_in[7];
    const float* g2        = (const float*)d_in[8];
    const float* b2        = (const float*)d_in[9];
    const float* projW     = (const float*)d_in[10];
    const float* projb     = (const float*)d_in[11];
    float* out = (float*)d_out;

    (void)in_sizes; (void)n_in;

    cudaFuncSetAttribute(conv_mma_kernel, cudaFuncAttributeMaxDynamicSharedMemorySize, CONV_SMEM);

    float *buf0, *buf1, *wst;
    cudaGetSymbolAddress((void**)&buf0, g_buf0);
    cudaGetSymbolAddress((void**)&buf1, g_buf1);
    cudaGetSymbolAddress((void**)&wst,  g_Wst);

    const int fusedElems = BATCH * NQ * CDIM;
    const int idxElems   = BATCH * NQ * KP * 4;
    int writeIdx = (out_size >= fusedElems + idxElems) ? 1 : 0;

    const int convBlocks = (MROWS + 127) / 128;          // 1563
    const int n4         = MROWS * CDIM / 4;             // 3,200,000
    const int bnBlocks   = (n4 + 255) / 256;

    // prep
    init_grid_kernel<<<GRIDCELLS / 256, 256>>>();
    scatter_kernel<<<(MROWS + 255) / 256, 256>>>(vcoords);
    transposeW_kernel<<<16, 256>>>(projW);
    prepW_kernel<<<432, 256>>>(W1, wst);
    prepW_kernel<<<432, 256>>>(W2, wst + 27 * 4096);
    round_kernel<<<bnBlocks, 256>>>(vfeat, buf1, n4);    // tf32-rounded conv1 input

    // layer 1
    conv_mma_kernel<<<convBlocks, 256, CONV_SMEM>>>(buf1, vcoords, wst, buf0);
    reduce_partial_kernel<<<RBLOCKS, 256>>>(buf0);
    reduce_final_kernel<<<1, 64>>>(g1, b1);
    bn_apply_kernel<<<bnBlocks, 256>>>(buf0, buf1, n4, 1);   // rounded: feeds conv2

    // layer 2
    conv_mma_kernel<<<convBlocks, 256, CONV_SMEM>>>(buf1, vcoords, wst + 27 * 4096, buf0);
    reduce_partial_kernel<<<RBLOCKS, 256>>>(buf0);
    reduce_final_kernel<<<1, 64>>>(g2, b2);
    bn_apply_kernel<<<bnBlocks, 256>>>(buf0, buf1, n4, 0);   // exact: feeds fuse

    // fuse + project (+ voxel_indices)
    fuse_kernel<<<BATCH * NQ, 64>>>(keypoints, query, buf1, projb,
                                    out, out + fusedElems, writeIdx);
}